// round 6
// baseline (speedup 1.0000x reference)
#include <cuda_runtime.h>
#include <cuda_bf16.h>
#include <math_constants.h>

#define BQ 64
#define LQ 32
#define BD 128
#define LD 192
#define TOK_D 32
#define CLS_D 768

// Per-doc sorted (id<<8 | j) keys, padded to 256 with 0xFFFFFFFF
__device__ unsigned g_skeys[BD * 256];
// Per-doc bucket table: lower-bound index of id-bucket (id>>5), 160 buckets
__device__ unsigned char g_starts[BD * 160];
// Split-K CLS GEMM partials: 4 K-splits of qcls @ dcls^T
__device__ float g_clsp[4][BQ * BD];

// ---------------------------------------------------------------------------
// Kernel 1 (one launch, two block roles):
//   blocks [0,128):    per-doc rank-sort of keys + bucket table
//   blocks [128,256):  CLS GEMM, 16x16 output tile x 4-way split-K
// ---------------------------------------------------------------------------
__global__ __launch_bounds__(256) void prep_kernel(
    const int* __restrict__ doc_ids,     // [BD, LD]
    const float* __restrict__ qcls,      // [BQ, CLS_D]
    const float* __restrict__ dcls)      // [BD, CLS_D]
{
    __shared__ float smem[2 * 16 * 68];  // 8704B, aliased by both roles
    const int t = threadIdx.x;

    if (blockIdx.x < BD) {
        // ---------------- sort role ----------------
        unsigned* kk  = (unsigned*)smem;         // [192]
        unsigned* srt = (unsigned*)smem + 192;   // [256]
        const int d = blockIdx.x;

        if (t < LD) {
            kk[t] = ((unsigned)doc_ids[d * LD + t] << 8) | (unsigned)t;
        } else {
            srt[t] = 0xFFFFFFFFu;                // pad slots 192..255
        }
        __syncthreads();

        if (t < LD) {
            const unsigned mine = kk[t];
            int rank = 0;
#pragma unroll 8
            for (int o = 0; o < LD; o++) rank += (kk[o] < mine) ? 1 : 0;
            srt[rank] = mine;
        }
        __syncthreads();

        g_skeys[d * 256 + t] = srt[t];
        if (t < 160) {
            const unsigned target = (unsigned)t << 13;  // (bucket<<5)<<8
            int idx = 0;
#pragma unroll
            for (int s = 128; s; s >>= 1) {
                if (srt[idx + s - 1] < target) idx += s;
            }
            g_starts[d * 160 + t] = (unsigned char)idx;
        }
    } else {
        // ---------------- CLS GEMM role ----------------
        // 32 output tiles (4 q-tiles x 8 d-tiles of 16x16) x 4 K-splits
        const int bx2  = blockIdx.x - BD;   // 0..127
        const int ks   = bx2 & 3;
        const int tile = bx2 >> 2;
        const int q0   = (tile >> 3) * 16;
        const int d0   = (tile & 7) * 16;

        float* sa = smem;               // [16][68]
        float* sb = smem + 16 * 68;     // [16][68]

        const int r  = t >> 4;          // load row 0..15
        const int c4 = t & 15;          // float4 column 0..15
        const int ty = t >> 4;          // out q within tile
        const int tx = t & 15;          // out d within tile

        float acc = 0.0f;
#pragma unroll
        for (int c = 0; c < 3; c++) {
            const int kb = ks * 192 + c * 64;
            const float4 av = *(const float4*)(qcls + (q0 + r) * CLS_D + kb + c4 * 4);
            const float4 bv = *(const float4*)(dcls + (d0 + r) * CLS_D + kb + c4 * 4);
            ((float4*)(sa + r * 68))[c4] = av;
            ((float4*)(sb + r * 68))[c4] = bv;
            __syncthreads();
#pragma unroll
            for (int k = 0; k < 64; k++) {
                acc = fmaf(sa[ty * 68 + k], sb[tx * 68 + k], acc);
            }
            __syncthreads();
        }
        g_clsp[ks][(q0 + ty) * BD + (d0 + tx)] = acc;
    }
}

// ---------------------------------------------------------------------------
// Kernel 2: one warp per (q, d), lane = query position i.
//   block = (d, 8 queries), grid = (128, 8), 256 threads.
// ---------------------------------------------------------------------------
__global__ __launch_bounds__(256) void coil_token_kernel(
    const float* __restrict__ qtok,   // [BQ, LQ, TOK_D]
    const float* __restrict__ dtok,   // [BD, LD, TOK_D]
    const int*   __restrict__ qids,   // [BQ, LQ]
    const int*   __restrict__ qmask,  // [BQ, LQ]
    float*       __restrict__ out)    // [BQ, BD]
{
    __shared__ unsigned skeys[256];
    __shared__ unsigned char sstart[160];
    const int d = blockIdx.x;
    const int t = threadIdx.x;

    skeys[t] = g_skeys[d * 256 + t];
    if (t < 160) sstart[t] = g_starts[d * 160 + t];
    __syncthreads();

    const int warp = t >> 5;
    const int lane = t & 31;
    const int q = blockIdx.y * 8 + warp;

    // mask with SEP position zeroed (sep = sum(mask) - 1)
    const int mv = qmask[q * LQ + lane];
    const int tot = __reduce_add_sync(0xFFFFFFFFu, mv);
    const float qmf = (lane == tot - 1) ? 0.0f : (float)mv;

    const unsigned qid = (unsigned)qids[q * LQ + lane];

    // bucket start + short scan to lower bound of qid
    int idx = sstart[qid >> 5];
    while ((skeys[idx] >> 8) < qid) idx++;

    // consume matching run (avg ~0.04 matches per lane)
    float mneg = -CUDART_INF_F;
    int nmatch = 0;
    const float4* qe = (const float4*)(qtok + (q * LQ + lane) * TOK_D);
    while ((skeys[idx] >> 8) == qid) {
        const int j = (int)(skeys[idx] & 0xFFu);
        const float4* de = (const float4*)(dtok + (d * LD + j) * TOK_D);
        float s0 = 0.0f;
#pragma unroll
        for (int e = 0; e < TOK_D / 4; e++) {
            const float4 a = qe[e];
            const float4 b = de[e];
            s0 += a.x * b.x + a.y * b.y + a.z * b.z + a.w * b.w;
        }
        mneg = fmaxf(mneg, s0);
        nmatch++;
        idx++;
    }
    // where(match, s, 0).max: zeros participate iff any non-match exists
    const float m = (nmatch < LD) ? fmaxf(mneg, 0.0f) : mneg;

    // drop CLS position (i==0), weight by mask; fold CLS GEMM partials into
    // lanes 0..3 so the single warp reduction covers everything
    float total = (lane >= 1) ? m * qmf : 0.0f;
    if (lane < 4) total += g_clsp[lane][q * BD + d];

#pragma unroll
    for (int s = 16; s; s >>= 1) total += __shfl_xor_sync(0xFFFFFFFFu, total, s);
    if (lane == 0) out[q * BD + d] = total;
}

// ---------------------------------------------------------------------------
extern "C" void kernel_launch(void* const* d_in, const int* in_sizes, int n_in,
                              void* d_out, int out_size) {
    const float* qtok  = (const float*)d_in[0];
    const float* dtok  = (const float*)d_in[1];
    const float* qcls  = (const float*)d_in[2];
    const float* dcls  = (const float*)d_in[3];
    const int*   qids  = (const int*)d_in[4];
    const int*   dids  = (const int*)d_in[5];
    const int*   qmask = (const int*)d_in[6];
    float* out = (float*)d_out;

    prep_kernel<<<2 * BD, 256>>>(dids, qcls, dcls);
    dim3 grid(BD, BQ / 8);
    coil_token_kernel<<<grid, 256>>>(qtok, dtok, qids, qmask, out);
}

// round 7
// speedup vs baseline: 1.0367x; 1.0367x over previous
#include <cuda_runtime.h>
#include <cuda_bf16.h>
#include <math_constants.h>

#define BQ 64
#define LQ 32
#define BD 128
#define LD 192
#define TOK_D 32
#define CLS_D 768

// Split-K8 CLS GEMM partials
__device__ float g_clsp8[8][BQ * BD];

// Order-preserving uint encoding of float (monotonic for all finite values)
__device__ __forceinline__ unsigned enc_f(float f) {
    unsigned b = __float_as_uint(f);
    return (b & 0x80000000u) ? ~b : (b | 0x80000000u);
}
__device__ __forceinline__ float dec_f(unsigned u) {
    return __uint_as_float((u & 0x80000000u) ? (u ^ 0x80000000u) : ~u);
}

// ---------------------------------------------------------------------------
// Kernel 1: CLS GEMM  qcls[64,768] @ dcls[128,768]^T, split-K8.
// 256 blocks x 64 threads. Tile 16q x 16d, 2x2 register tile per thread.
// ---------------------------------------------------------------------------
__global__ __launch_bounds__(64) void cls_gemm_kernel(
    const float* __restrict__ qcls, const float* __restrict__ dcls)
{
    __shared__ float sa[96 * 18];   // k-major, pitch 18
    __shared__ float sb[96 * 18];

    const int b = blockIdx.x;
    const int split = b & 7;
    const int tile  = b >> 3;
    const int q0 = (tile >> 3) * 16;
    const int d0 = (tile & 7) * 16;
    const int kb = split * 96;
    const int t  = threadIdx.x;

    // Stage 16 rows x 96 cols of each matrix, transposed to k-major
#pragma unroll
    for (int f = 0; f < 6; f++) {
        const int fi  = t * 6 + f;       // 0..383
        const int row = fi / 24;
        const int c4  = fi % 24;
        const float4 a  = *(const float4*)(qcls + (q0 + row) * CLS_D + kb + c4 * 4);
        const float4 bv = *(const float4*)(dcls + (d0 + row) * CLS_D + kb + c4 * 4);
        const int k = c4 * 4;
        sa[(k + 0) * 18 + row] = a.x;  sa[(k + 1) * 18 + row] = a.y;
        sa[(k + 2) * 18 + row] = a.z;  sa[(k + 3) * 18 + row] = a.w;
        sb[(k + 0) * 18 + row] = bv.x; sb[(k + 1) * 18 + row] = bv.y;
        sb[(k + 2) * 18 + row] = bv.z; sb[(k + 3) * 18 + row] = bv.w;
    }
    __syncthreads();

    const int ty = t >> 3;   // 0..7
    const int tx = t & 7;    // 0..7
    float a00 = 0.f, a01 = 0.f, a10 = 0.f, a11 = 0.f;
#pragma unroll 4
    for (int k = 0; k < 96; k++) {
        const float2 rA = *(const float2*)&sa[k * 18 + ty * 2];
        const float2 rB = *(const float2*)&sb[k * 18 + tx * 2];
        a00 = fmaf(rA.x, rB.x, a00);
        a01 = fmaf(rA.x, rB.y, a01);
        a10 = fmaf(rA.y, rB.x, a10);
        a11 = fmaf(rA.y, rB.y, a11);
    }
    const int qq = q0 + ty * 2, dd = d0 + tx * 2;
    g_clsp8[split][(qq + 0) * BD + dd + 0] = a00;
    g_clsp8[split][(qq + 0) * BD + dd + 1] = a01;
    g_clsp8[split][(qq + 1) * BD + dd + 0] = a10;
    g_clsp8[split][(qq + 1) * BD + dd + 1] = a11;
}

// ---------------------------------------------------------------------------
// Kernel 2: one block per doc (128 blocks x 512 threads).
//   phase 0: stage dtok tile, doc keys, zero slots, prefetch per-warp data
//   phase 1: rank-sort keys; bucket table
//   phase A: per warp (4 queries): search sorted keys, emit match records
//   phase B: one thread per record: 32-dim dot, atomicMax into (q,i) slot
//   phase C: per warp: gather slots, weights, CLS partials, butterfly, store
// ---------------------------------------------------------------------------
__global__ __launch_bounds__(512) void coil_doc_kernel(
    const float* __restrict__ qtok,   // [BQ, LQ, TOK_D]
    const float* __restrict__ dtok,   // [BD, LD, TOK_D]
    const int*   __restrict__ qids,   // [BQ, LQ]
    const int*   __restrict__ dids,   // [BD, LD]
    const int*   __restrict__ qmask,  // [BQ, LQ]
    float*       __restrict__ out)    // [BQ, BD]
{
    __shared__ float    dtokS[LD * TOK_D];        // 24 KB
    __shared__ unsigned keysS[LD];
    __shared__ unsigned srt[256];                  // sorted keys + pad
    __shared__ unsigned char sstart[160];
    __shared__ unsigned mslot[BQ * LQ];            // 8 KB, enc-float max slots
    __shared__ unsigned mlist[2048];               // 8 KB match records
    __shared__ int mcountS;
    __shared__ int allsameS, docIdS;

    const int d    = blockIdx.x;
    const int t    = threadIdx.x;
    const int w    = t >> 5;
    const int lane = t & 31;

    // ---- per-warp prefetch (independent of smem) ----
    int   qid4[4], qm4[4];
    float cp4[4];
#pragma unroll
    for (int k = 0; k < 4; k++) {
        const int q = w * 4 + k;
        qid4[k] = qids[q * LQ + lane];
        qm4[k]  = qmask[q * LQ + lane];
        cp4[k]  = (lane < 8) ? g_clsp8[lane][q * BD + d] : 0.0f;
    }

    // ---- phase 0: staging ----
    if (t < LD) {
        keysS[t] = ((unsigned)dids[d * LD + t] << 8) | (unsigned)t;
    } else if (t < 256) {
        srt[t] = 0xFFFFFFFFu;                       // pad slots 192..255
    }
#pragma unroll
    for (int f = 0; f < 3; f++) {                   // 1536 float4 total
        const int fi = t + f * 512;
        ((float4*)dtokS)[fi] = ((const float4*)(dtok + d * LD * TOK_D))[fi];
    }
#pragma unroll
    for (int f = 0; f < 4; f++) mslot[t + f * 512] = 0u;
    if (t == 0) mcountS = 0;
    __syncthreads();

    // ---- phase 1: rank sort (keys unique: j in low bits) ----
    if (t < LD) {
        const unsigned mine = keysS[t];
        int rank = 0;
        const uint4* k4 = (const uint4*)keysS;
#pragma unroll 8
        for (int o = 0; o < LD / 4; o++) {
            const uint4 kk = k4[o];
            rank += (kk.x < mine) + (kk.y < mine) + (kk.z < mine) + (kk.w < mine);
        }
        srt[rank] = mine;
    }
    __syncthreads();

    // ---- phase 1b: bucket table (lower bound of id-bucket id>>5) ----
    if (t < 160) {
        const unsigned target = (unsigned)t << 13;
        int idx = 0;
#pragma unroll
        for (int s = 128; s; s >>= 1) {
            if (srt[idx + s - 1] < target) idx += s;
        }
        sstart[t] = (unsigned char)idx;
    }
    if (t == 0) {
        docIdS = (int)(srt[0] >> 8);
        allsameS = (srt[0] >> 8) == (srt[LD - 1] >> 8);
    }
    __syncthreads();

    // ---- phase A: search & emit match records ----
#pragma unroll
    for (int k = 0; k < 4; k++) {
        const int q = w * 4 + k;
        const unsigned qid = (unsigned)qid4[k];
        int idx = sstart[qid >> 5];
        while ((srt[idx] >> 8) < qid) idx++;
        while ((srt[idx] >> 8) == qid) {
            const int pos = atomicAdd(&mcountS, 1) & 2047;
            mlist[pos] = ((unsigned)q << 13) | ((unsigned)lane << 8) | (srt[idx] & 0xFFu);
            idx++;
        }
    }
    __syncthreads();

    // ---- phase B: process records (one thread each) ----
    const int mc = min(mcountS, 2048);
    for (int r = t; r < mc; r += 512) {
        const unsigned rec = mlist[r];
        const int q = (int)(rec >> 13);
        const int i = (int)((rec >> 8) & 31u);
        const int j = (int)(rec & 0xFFu);
        const float4* qr = (const float4*)(qtok + (q * LQ + i) * TOK_D);
        const float4* dr = (const float4*)(dtokS + j * TOK_D);
        float s = 0.f;
#pragma unroll
        for (int e = 0; e < TOK_D / 4; e++) {
            const float4 a = qr[e];
            const float4 b = dr[e];
            s += a.x * b.x + a.y * b.y + a.z * b.z + a.w * b.w;
        }
        atomicMax(&mslot[q * LQ + i], enc_f(s));
    }
    __syncthreads();

    // ---- phase C: per-query reduction + CLS + store ----
    float v[4];
#pragma unroll
    for (int k = 0; k < 4; k++) {
        const int q = w * 4 + k;
        const int tot = __reduce_add_sync(0xFFFFFFFFu, qm4[k]);
        const float qmf = (lane == tot - 1) ? 0.0f : (float)qm4[k];

        const unsigned slot = mslot[q * LQ + lane];
        float val;
        if (slot == 0u) {
            val = 0.0f;                      // no match: row of zeros -> max 0
        } else {
            const float mm = dec_f(slot);
            // all 192 doc tokens match this id -> no zero participates in max
            const bool full = allsameS && (qid4[k] == docIdS);
            val = full ? mm : fmaxf(mm, 0.0f);
        }
        v[k] = (lane >= 1) ? val * qmf : 0.0f;
        if (lane < 8) v[k] += cp4[k];        // fold CLS split-K partials
    }
#pragma unroll
    for (int s = 16; s; s >>= 1) {
#pragma unroll
        for (int k = 0; k < 4; k++) v[k] += __shfl_xor_sync(0xFFFFFFFFu, v[k], s);
    }
    if (lane == 0) {
#pragma unroll
        for (int k = 0; k < 4; k++) out[(w * 4 + k) * BD + d] = v[k];
    }
}

// ---------------------------------------------------------------------------
extern "C" void kernel_launch(void* const* d_in, const int* in_sizes, int n_in,
                              void* d_out, int out_size) {
    const float* qtok  = (const float*)d_in[0];
    const float* dtok  = (const float*)d_in[1];
    const float* qcls  = (const float*)d_in[2];
    const float* dcls  = (const float*)d_in[3];
    const int*   qids  = (const int*)d_in[4];
    const int*   dids  = (const int*)d_in[5];
    const int*   qmask = (const int*)d_in[6];
    float* out = (float*)d_out;

    cls_gemm_kernel<<<256, 64>>>(qcls, dcls);
    coil_doc_kernel<<<BD, 512>>>(qtok, dtok, qids, dids, qmask, out);
}

// round 9
// speedup vs baseline: 1.3953x; 1.3459x over previous
#include <cuda_runtime.h>
#include <cuda_bf16.h>
#include <math_constants.h>

#define BQ 64
#define LQ 32
#define BD 128
#define LD 192
#define TOK_D 32
#define CLS_D 768

// Order-preserving uint encoding of float (monotonic for all finite values)
__device__ __forceinline__ unsigned enc_f(float f) {
    unsigned b = __float_as_uint(f);
    return (b & 0x80000000u) ? ~b : (b | 0x80000000u);
}
__device__ __forceinline__ float dec_f(unsigned u) {
    return __uint_as_float((u & 0x80000000u) ? (u ^ 0x80000000u) : ~u);
}

// ---------------------------------------------------------------------------
// Single fused kernel: one block per doc (128 blocks x 512 threads).
//   phase 0: stage dtok tile + dcls row + doc keys, zero slots, prefetch
//   phase 1: rank-sort keys (warps 0..5)  ||  CLS dots (all warps, LDG-heavy)
//   phase A: 4 register-interleaved binary searches per warp, emit records
//   phase B: one thread per record: 32-dim dot, atomicMax into (q,i) slot
//   phase C: per warp: slots + mask + CLS partial, butterfly, store
// ---------------------------------------------------------------------------
__global__ __launch_bounds__(512) void coil_fused_kernel(
    const float* __restrict__ qtok,   // [BQ, LQ, TOK_D]
    const float* __restrict__ dtok,   // [BD, LD, TOK_D]
    const float* __restrict__ qcls,   // [BQ, CLS_D]
    const float* __restrict__ dcls,   // [BD, CLS_D]
    const int*   __restrict__ qids,   // [BQ, LQ]
    const int*   __restrict__ dids,   // [BD, LD]
    const int*   __restrict__ qmask,  // [BQ, LQ]
    float*       __restrict__ out)    // [BQ, BD]
{
    __shared__ float    dtokS[LD * TOK_D];        // 24 KB
    __shared__ float    dclsS[CLS_D];             // 3 KB
    __shared__ unsigned keysS[LD];
    __shared__ unsigned srt[256];                  // sorted keys + pad
    __shared__ unsigned mslot[BQ * LQ];            // 8 KB enc-float max slots
    __shared__ unsigned mlist[2048];               // 8 KB match records
    __shared__ int mcountS;
    __shared__ int allsameS, docIdS;

    const int d    = blockIdx.x;
    const int t    = threadIdx.x;
    const int w    = t >> 5;
    const int lane = t & 31;

    // ---- per-warp prefetch (no smem dependence) ----
    int qid4[4], qm4[4];
#pragma unroll
    for (int k = 0; k < 4; k++) {
        const int q = w * 4 + k;
        qid4[k] = qids[q * LQ + lane];
        qm4[k]  = qmask[q * LQ + lane];
    }

    // ---- phase 0: staging ----
    if (t < LD) {
        keysS[t] = ((unsigned)dids[d * LD + t] << 8) | (unsigned)t;
    } else if (t < 256) {
        srt[t] = 0xFFFFFFFFu;                       // pad slots 192..255
    }
#pragma unroll
    for (int f = 0; f < 3; f++) {                   // 1536 float4 of dtok tile
        const int fi = t + f * 512;
        ((float4*)dtokS)[fi] = ((const float4*)(dtok + d * LD * TOK_D))[fi];
    }
    if (t < CLS_D / 4) {                            // 192 float4 of dcls row
        ((float4*)dclsS)[t] = ((const float4*)(dcls + d * CLS_D))[t];
    }
#pragma unroll
    for (int f = 0; f < 4; f++) mslot[t + f * 512] = 0u;
    if (t == 0) mcountS = 0;
    __syncthreads();

    // ---- phase 1a: CLS dots (all warps). lane covers dims {c*128 + lane*4} ----
    float4 bv[6];
#pragma unroll
    for (int c = 0; c < 6; c++) bv[c] = ((const float4*)dclsS)[c * 32 + lane];
    float cls4[4];
#pragma unroll
    for (int k = 0; k < 4; k++) {
        const int q = w * 4 + k;
        const float4* qc = (const float4*)(qcls + q * CLS_D);
        float acc = 0.0f;
#pragma unroll
        for (int c = 0; c < 6; c++) {
            const float4 a = qc[c * 32 + lane];
            acc += a.x * bv[c].x + a.y * bv[c].y + a.z * bv[c].z + a.w * bv[c].w;
        }
        cls4[k] = acc;
    }

    // ---- phase 1b: rank sort (threads < 192; keys unique: j in low bits) ----
    if (t < LD) {
        const unsigned mine = keysS[t];
        int rank = 0;
        const uint4* k4 = (const uint4*)keysS;
#pragma unroll 8
        for (int o = 0; o < LD / 4; o++) {
            const uint4 kk = k4[o];
            rank += (kk.x < mine) + (kk.y < mine) + (kk.z < mine) + (kk.w < mine);
        }
        srt[rank] = mine;
    }
    __syncthreads();

    // ---- phase A: 4 interleaved binary searches + emit records ----
    if (t == 511) {
        docIdS = (int)(srt[0] >> 8);
        allsameS = (srt[0] >> 8) == (srt[LD - 1] >> 8);
    }
    unsigned tgt[4];
    int idx[4];
#pragma unroll
    for (int k = 0; k < 4; k++) { tgt[k] = (unsigned)qid4[k] << 8; idx[k] = 0; }
#pragma unroll
    for (int s = 128; s; s >>= 1) {
#pragma unroll
        for (int k = 0; k < 4; k++) {
            if (srt[idx[k] + s - 1] < tgt[k]) idx[k] += s;
        }
    }
#pragma unroll
    for (int k = 0; k < 4; k++) {
        const int q = w * 4 + k;
        int i2 = idx[k];
        while ((srt[i2] >> 8) == (unsigned)qid4[k]) {
            const int pos = atomicAdd(&mcountS, 1) & 2047;
            mlist[pos] = ((unsigned)q << 13) | ((unsigned)lane << 8) | (srt[i2] & 0xFFu);
            i2++;
        }
    }
    __syncthreads();

    // ---- phase B: process records (one thread each; ~79 expected) ----
    const int mc = min(mcountS, 2048);
    for (int r = t; r < mc; r += 512) {
        const unsigned rec = mlist[r];
        const int q = (int)(rec >> 13);
        const int i = (int)((rec >> 8) & 31u);
        const int j = (int)(rec & 0xFFu);
        const float4* qr = (const float4*)(qtok + (q * LQ + i) * TOK_D);
        const float4* dr = (const float4*)(dtokS + j * TOK_D);
        float s = 0.f;
#pragma unroll
        for (int e = 0; e < TOK_D / 4; e++) {
            const float4 a = qr[e];
            const float4 b = dr[e];
            s += a.x * b.x + a.y * b.y + a.z * b.z + a.w * b.w;
        }
        atomicMax(&mslot[q * LQ + i], enc_f(s));
    }
    __syncthreads();

    // ---- phase C: per-query combine + butterfly + store ----
    float v[4];
#pragma unroll
    for (int k = 0; k < 4; k++) {
        const int q = w * 4 + k;
        const int tot = __reduce_add_sync(0xFFFFFFFFu, qm4[k]);
        const float qmf = (lane == tot - 1) ? 0.0f : (float)qm4[k];

        const unsigned slot = mslot[q * LQ + lane];
        float val;
        if (slot == 0u) {
            val = 0.0f;                      // no match: row of zeros -> max 0
        } else {
            const float mm = dec_f(slot);
            // all 192 doc tokens match this id -> no zero participates in max
            const bool full = allsameS && (qid4[k] == docIdS);
            val = full ? mm : fmaxf(mm, 0.0f);
        }
        v[k] = ((lane >= 1) ? val * qmf : 0.0f) + cls4[k];
    }
#pragma unroll
    for (int s = 16; s; s >>= 1) {
#pragma unroll
        for (int k = 0; k < 4; k++) v[k] += __shfl_xor_sync(0xFFFFFFFFu, v[k], s);
    }
    if (lane == 0) {
#pragma unroll
        for (int k = 0; k < 4; k++) out[(w * 4 + k) * BD + d] = v[k];
    }
}

// ---------------------------------------------------------------------------
extern "C" void kernel_launch(void* const* d_in, const int* in_sizes, int n_in,
                              void* d_out, int out_size) {
    const float* qtok  = (const float*)d_in[0];
    const float* dtok  = (const float*)d_in[1];
    const float* qcls  = (const float*)d_in[2];
    const float* dcls  = (const float*)d_in[3];
    const int*   qids  = (const int*)d_in[4];
    const int*   dids  = (const int*)d_in[5];
    const int*   qmask = (const int*)d_in[6];
    float* out = (float*)d_out;

    coil_fused_kernel<<<BD, 512>>>(qtok, dtok, qcls, dcls, qids, dids, qmask, out);
}